// round 4
// baseline (speedup 1.0000x reference)
#include <cuda_runtime.h>
#include <math.h>

#define BATCH 2
#define SEQ   2048
#define EMB   1024
#define NH    16
#define HD    64
#define MTOT  (BATCH*SEQ)   // 4096

// ---------------- device scratch (no allocations allowed) ----------------
__device__ float g_Qt[(size_t)BATCH * NH * HD * SEQ];   // [B,H,Dh,S]  (transposed, pre-scaled at use)
__device__ float g_Kt[(size_t)BATCH * NH * HD * SEQ];   // [B,H,Dh,S]  (transposed)
__device__ float g_V [(size_t)BATCH * NH * SEQ * HD];   // [B,H,S,Dh]
__device__ float g_ctx[(size_t)MTOT * EMB];             // [B*S, E] head-concat

// =========================================================================
// Kernel 1: fused QKV projection.
//   C[4096 x 64] = X[4096 x 1024] * W_h[1024 x 64] + bias_h
//   z = 0 (Q, transposed out), 1 (K, transposed out), 2 (V, normal out)
// Tile 128x64, Kblk=16, 256 threads, 8x4 frags, register prefetch.
// =========================================================================
__global__ __launch_bounds__(256) void proj_qkv_kernel(
    const float* __restrict__ qin, const float* __restrict__ kin, const float* __restrict__ vin,
    const float* __restrict__ Wq,  const float* __restrict__ Wk,  const float* __restrict__ Wv,
    const float* __restrict__ bq,  const float* __restrict__ bk,  const float* __restrict__ bv)
{
    __shared__ float smem[8320];          // max(As+Bs = 3136, Cs = 128*65 = 8320)
    float* As = smem;                     // [16][132]  (transposed A tile, pitch 132)
    float* Bs = smem + 2112;              // [16][64]
    float* Cs = smem;                     // [128][65]  reused after main loop

    const int z  = blockIdx.z;
    const int h  = blockIdx.y;
    const int mb = blockIdx.x;

    const float* A    = (z == 0) ? qin : (z == 1) ? kin : vin;
    const float* W    = ((z == 0) ? Wq : (z == 1) ? Wk : Wv) + (size_t)h * EMB * HD;
    const float* bias = ((z == 0) ? bq : (z == 1) ? bk : bv) + h * HD;

    const int tid = threadIdx.x;
    const int tn  = tid & 15;             // frag col group (4 cols)
    const int tm  = tid >> 4;             // frag row group (8 rows)
    const int lc  = tid & 3;              // A-loader k-quad
    const int lm  = tid >> 2;             // A-loader row (0..63), + 64
    const int bkr = tid >> 4;             // B-loader k row

    const float* Ag = A + (size_t)(mb * 128) * EMB;

    float acc[8][4];
    #pragma unroll
    for (int i = 0; i < 8; i++)
        #pragma unroll
        for (int j = 0; j < 4; j++) acc[i][j] = 0.f;

    // prefetch first tiles into registers
    float4 pa0 = *(const float4*)(Ag + (size_t)lm        * EMB + lc * 4);
    float4 pa1 = *(const float4*)(Ag + (size_t)(lm + 64) * EMB + lc * 4);
    float4 pb  = *(const float4*)(W  + (size_t)bkr * HD + tn * 4);

    for (int k0 = 0; k0 < EMB; k0 += 16) {
        __syncthreads();
        // store A transposed: As[k][m], pitch 132
        As[(lc * 4 + 0) * 132 + lm] = pa0.x;
        As[(lc * 4 + 1) * 132 + lm] = pa0.y;
        As[(lc * 4 + 2) * 132 + lm] = pa0.z;
        As[(lc * 4 + 3) * 132 + lm] = pa0.w;
        As[(lc * 4 + 0) * 132 + lm + 64] = pa1.x;
        As[(lc * 4 + 1) * 132 + lm + 64] = pa1.y;
        As[(lc * 4 + 2) * 132 + lm + 64] = pa1.z;
        As[(lc * 4 + 3) * 132 + lm + 64] = pa1.w;
        *(float4*)(Bs + bkr * 64 + tn * 4) = pb;
        __syncthreads();

        const int kn = k0 + 16;
        if (kn < EMB) {                   // prefetch next tiles (hidden under FFMA below)
            pa0 = *(const float4*)(Ag + (size_t)lm        * EMB + kn + lc * 4);
            pa1 = *(const float4*)(Ag + (size_t)(lm + 64) * EMB + kn + lc * 4);
            pb  = *(const float4*)(W  + (size_t)(kn + bkr) * HD + tn * 4);
        }

        #pragma unroll
        for (int kk = 0; kk < 16; kk++) {
            float4 a0 = *(const float4*)(As + kk * 132 + tm * 8);
            float4 a1 = *(const float4*)(As + kk * 132 + tm * 8 + 4);
            float4 b  = *(const float4*)(Bs + kk * 64 + tn * 4);
            float av[8] = {a0.x, a0.y, a0.z, a0.w, a1.x, a1.y, a1.z, a1.w};
            #pragma unroll
            for (int i = 0; i < 8; i++) {
                acc[i][0] = fmaf(av[i], b.x, acc[i][0]);
                acc[i][1] = fmaf(av[i], b.y, acc[i][1]);
                acc[i][2] = fmaf(av[i], b.z, acc[i][2]);
                acc[i][3] = fmaf(av[i], b.w, acc[i][3]);
            }
        }
    }

    // bias
    float4 bb = *(const float4*)(bias + tn * 4);
    #pragma unroll
    for (int i = 0; i < 8; i++) {
        acc[i][0] += bb.x; acc[i][1] += bb.y; acc[i][2] += bb.z; acc[i][3] += bb.w;
    }

    const int gm0 = mb * 128;
    const int b   = gm0 >> 11;            // batch (tiles never straddle)
    const int s0  = gm0 & 2047;

    if (z == 2) {
        // V: normal layout [B,H,S,Dh]
        float* Vout = g_V + ((size_t)(b * NH + h) * SEQ + s0) * HD;
        #pragma unroll
        for (int i = 0; i < 8; i++) {
            float4 v4 = make_float4(acc[i][0], acc[i][1], acc[i][2], acc[i][3]);
            *(float4*)(Vout + (size_t)(tm * 8 + i) * HD + tn * 4) = v4;
        }
    } else {
        // Q/K: transposed layout [B,H,Dh,S] via smem staging (pitch 65 kills conflicts)
        __syncthreads();
        #pragma unroll
        for (int i = 0; i < 8; i++)
            #pragma unroll
            for (int j = 0; j < 4; j++)
                Cs[(tm * 8 + i) * 65 + tn * 4 + j] = acc[i][j];
        __syncthreads();

        float* outT = ((z == 0) ? g_Qt : g_Kt) + (size_t)(b * NH + h) * HD * SEQ + s0;
        const int dlo = tid >> 5;         // 0..7
        const int s4  = (tid & 31) * 4;   // 0..124
        #pragma unroll
        for (int p = 0; p < 8; p++) {
            int dd = dlo + p * 8;
            float4 v4;
            v4.x = Cs[(s4 + 0) * 65 + dd];
            v4.y = Cs[(s4 + 1) * 65 + dd];
            v4.z = Cs[(s4 + 2) * 65 + dd];
            v4.w = Cs[(s4 + 3) * 65 + dd];
            *(float4*)(outT + (size_t)dd * SEQ + s4) = v4;
        }
    }
}

// =========================================================================
// Kernel 2: flash attention, fp32.
//   Per block: 64 query rows of one (b,h); sweep K/V in 64-wide tiles.
//   Qt/Kt are [Dh][S] so both GEMM fragments are float4 along free dims.
//   P overwrites the K smem buffer. Online softmax with 16-lane shuffles.
// =========================================================================
__global__ __launch_bounds__(256) void flash_kernel()
{
    extern __shared__ float sm[];
    float* Qs  = sm;            // [64][64]  Qt tile (pre-scaled by 1/sqrt(Dh))
    float* KPs = sm + 4096;     // [64][64]  Kt tile, then P tile
    float* Vs  = sm + 8192;     // [64][64]  V tile

    const int qb = blockIdx.x, h = blockIdx.y, b = blockIdx.z;
    const size_t bh = (size_t)(b * NH + h);
    const float* Qg = g_Qt + bh * HD * SEQ + qb * 64;
    const float* Kg = g_Kt + bh * HD * SEQ;
    const float* Vg = g_V  + bh * SEQ * HD;

    const int tid = threadIdx.x;
    const int tx = tid & 15, ty = tid >> 4;
    const int lr = tid >> 4, lc4 = (tid & 15) * 4;

    // load Q tile once, fold in 1/sqrt(64) = 0.125
    #pragma unroll
    for (int p = 0; p < 4; p++) {
        int d = lr + p * 16;
        float4 g = *(const float4*)(Qg + (size_t)d * SEQ + lc4);
        g.x *= 0.125f; g.y *= 0.125f; g.z *= 0.125f; g.w *= 0.125f;
        *(float4*)(Qs + d * 64 + lc4) = g;
    }

    float o[4][4];
    #pragma unroll
    for (int j = 0; j < 4; j++)
        #pragma unroll
        for (int i = 0; i < 4; i++) o[j][i] = 0.f;
    float m_r[4] = {-1e30f, -1e30f, -1e30f, -1e30f};
    float l_r[4] = {0.f, 0.f, 0.f, 0.f};

    for (int t0 = 0; t0 < SEQ; t0 += 64) {
        __syncthreads();   // Qs ready (1st iter) / previous PV reads of KPs,Vs done
        #pragma unroll
        for (int p = 0; p < 4; p++) {
            int r = lr + p * 16;
            *(float4*)(KPs + r * 64 + lc4) = *(const float4*)(Kg + (size_t)r * SEQ + t0 + lc4);
            *(float4*)(Vs  + r * 64 + lc4) = *(const float4*)(Vg + (size_t)(t0 + r) * HD + lc4);
        }
        __syncthreads();

        // S = Q K^T (scaled): inner over d
        float s[4][4];
        #pragma unroll
        for (int j = 0; j < 4; j++)
            #pragma unroll
            for (int i = 0; i < 4; i++) s[j][i] = 0.f;
        #pragma unroll 8
        for (int d = 0; d < 64; d++) {
            float4 a  = *(const float4*)(Qs  + d * 64 + ty * 4);  // 4 query rows @ this d
            float4 kv = *(const float4*)(KPs + d * 64 + tx * 4);  // 4 key cols  @ this d
            float ar[4] = {a.x, a.y, a.z, a.w};
            float kr[4] = {kv.x, kv.y, kv.z, kv.w};
            #pragma unroll
            for (int j = 0; j < 4; j++)
                #pragma unroll
                for (int i = 0; i < 4; i++)
                    s[j][i] = fmaf(ar[j], kr[i], s[j][i]);
        }

        // online softmax (replicated across the 16 tx lanes of each row group)
        #pragma unroll
        for (int j = 0; j < 4; j++) {
            float mx = fmaxf(fmaxf(s[j][0], s[j][1]), fmaxf(s[j][2], s[j][3]));
            mx = fmaxf(mx, __shfl_xor_sync(0xffffffffu, mx, 1));
            mx = fmaxf(mx, __shfl_xor_sync(0xffffffffu, mx, 2));
            mx = fmaxf(mx, __shfl_xor_sync(0xffffffffu, mx, 4));
            mx = fmaxf(mx, __shfl_xor_sync(0xffffffffu, mx, 8));
            float mn = fmaxf(m_r[j], mx);
            float sc = __expf(m_r[j] - mn);
            m_r[j] = mn;
            float rs = 0.f;
            #pragma unroll
            for (int i = 0; i < 4; i++) {
                s[j][i] = __expf(s[j][i] - mn);
                rs += s[j][i];
            }
            rs += __shfl_xor_sync(0xffffffffu, rs, 1);
            rs += __shfl_xor_sync(0xffffffffu, rs, 2);
            rs += __shfl_xor_sync(0xffffffffu, rs, 4);
            rs += __shfl_xor_sync(0xffffffffu, rs, 8);
            l_r[j] = l_r[j] * sc + rs;
            #pragma unroll
            for (int i = 0; i < 4; i++) o[j][i] *= sc;
        }

        __syncthreads();   // everyone done reading Kt before P overwrites it
        #pragma unroll
        for (int j = 0; j < 4; j++) {
            float4 p4 = make_float4(s[j][0], s[j][1], s[j][2], s[j][3]);
            *(float4*)(KPs + (ty * 4 + j) * 64 + tx * 4) = p4;
        }
        __syncthreads();

        // O += P V : inner over kk
        #pragma unroll 4
        for (int kk = 0; kk < 64; kk += 4) {
            float4 pa[4], vb[4];
            #pragma unroll
            for (int j = 0; j < 4; j++)
                pa[j] = *(const float4*)(KPs + (ty * 4 + j) * 64 + kk);
            #pragma unroll
            for (int i2 = 0; i2 < 4; i2++)
                vb[i2] = *(const float4*)(Vs + (kk + i2) * 64 + tx * 4);
            const float* vbp = (const float*)vb;
            #pragma unroll
            for (int j = 0; j < 4; j++) {
                float par[4] = {pa[j].x, pa[j].y, pa[j].z, pa[j].w};
                #pragma unroll
                for (int c = 0; c < 4; c++) {
                    float t = o[j][c];
                    t = fmaf(par[0], vbp[0 * 4 + c], t);
                    t = fmaf(par[1], vbp[1 * 4 + c], t);
                    t = fmaf(par[2], vbp[2 * 4 + c], t);
                    t = fmaf(par[3], vbp[3 * 4 + c], t);
                    o[j][c] = t;
                }
            }
        }
    }

    // normalize + write ctx (head-concat layout [B*S, E])
    float* Cg = g_ctx + ((size_t)b * SEQ + qb * 64) * EMB + h * HD;
    #pragma unroll
    for (int j = 0; j < 4; j++) {
        float inv = 1.0f / l_r[j];
        float4 r4 = make_float4(o[j][0] * inv, o[j][1] * inv, o[j][2] * inv, o[j][3] * inv);
        *(float4*)(Cg + (size_t)(ty * 4 + j) * EMB + tx * 4) = r4;
    }
}

// =========================================================================
// Kernel 3: output projection.  out[4096 x 1024] = ctx * Wo + bo
// Same GEMM structure as kernel 1, direct coalesced store.
// =========================================================================
__global__ __launch_bounds__(256) void outproj_kernel(
    const float* __restrict__ Wo, const float* __restrict__ bo, float* __restrict__ out)
{
    __shared__ float smem[3136];
    float* As = smem;                     // [16][132]
    float* Bs = smem + 2112;              // [16][64]

    const int nb = blockIdx.y;
    const int mb = blockIdx.x;
    const int tid = threadIdx.x;
    const int tn  = tid & 15;
    const int tm  = tid >> 4;
    const int lc  = tid & 3;
    const int lm  = tid >> 2;
    const int bkr = tid >> 4;

    const float* Ag = g_ctx + (size_t)(mb * 128) * EMB;
    const float* Bg = Wo + nb * 64;

    float acc[8][4];
    #pragma unroll
    for (int i = 0; i < 8; i++)
        #pragma unroll
        for (int j = 0; j < 4; j++) acc[i][j] = 0.f;

    float4 pa0 = *(const float4*)(Ag + (size_t)lm        * EMB + lc * 4);
    float4 pa1 = *(const float4*)(Ag + (size_t)(lm + 64) * EMB + lc * 4);
    float4 pb  = *(const float4*)(Bg + (size_t)bkr * EMB + tn * 4);

    for (int k0 = 0; k0 < EMB; k0 += 16) {
        __syncthreads();
        As[(lc * 4 + 0) * 132 + lm] = pa0.x;
        As[(lc * 4 + 1) * 132 + lm] = pa0.y;
        As[(lc * 4 + 2) * 132 + lm] = pa0.z;
        As[(lc * 4 + 3) * 132 + lm] = pa0.w;
        As[(lc * 4 + 0) * 132 + lm + 64] = pa1.x;
        As[(lc * 4 + 1) * 132 + lm + 64] = pa1.y;
        As[(lc * 4 + 2) * 132 + lm + 64] = pa1.z;
        As[(lc * 4 + 3) * 132 + lm + 64] = pa1.w;
        *(float4*)(Bs + bkr * 64 + tn * 4) = pb;
        __syncthreads();

        const int kn = k0 + 16;
        if (kn < EMB) {
            pa0 = *(const float4*)(Ag + (size_t)lm        * EMB + kn + lc * 4);
            pa1 = *(const float4*)(Ag + (size_t)(lm + 64) * EMB + kn + lc * 4);
            pb  = *(const float4*)(Bg + (size_t)(kn + bkr) * EMB + tn * 4);
        }

        #pragma unroll
        for (int kk = 0; kk < 16; kk++) {
            float4 a0 = *(const float4*)(As + kk * 132 + tm * 8);
            float4 a1 = *(const float4*)(As + kk * 132 + tm * 8 + 4);
            float4 b  = *(const float4*)(Bs + kk * 64 + tn * 4);
            float av[8] = {a0.x, a0.y, a0.z, a0.w, a1.x, a1.y, a1.z, a1.w};
            #pragma unroll
            for (int i = 0; i < 8; i++) {
                acc[i][0] = fmaf(av[i], b.x, acc[i][0]);
                acc[i][1] = fmaf(av[i], b.y, acc[i][1]);
                acc[i][2] = fmaf(av[i], b.z, acc[i][2]);
                acc[i][3] = fmaf(av[i], b.w, acc[i][3]);
            }
        }
    }

    float4 bb = *(const float4*)(bo + nb * 64 + tn * 4);
    float* Cg = out + (size_t)(mb * 128) * EMB + nb * 64;
    #pragma unroll
    for (int i = 0; i < 8; i++) {
        float4 v4 = make_float4(acc[i][0] + bb.x, acc[i][1] + bb.y,
                                acc[i][2] + bb.z, acc[i][3] + bb.w);
        *(float4*)(Cg + (size_t)(tm * 8 + i) * EMB + tn * 4) = v4;
    }
}

// =========================================================================
extern "C" void kernel_launch(void* const* d_in, const int* in_sizes, int n_in,
                              void* d_out, int out_size)
{
    const float* q  = (const float*)d_in[0];
    const float* k  = (const float*)d_in[1];
    const float* v  = (const float*)d_in[2];
    const float* Wq = (const float*)d_in[3];
    const float* Wk = (const float*)d_in[4];
    const float* Wv = (const float*)d_in[5];
    const float* bq = (const float*)d_in[6];
    const float* bk = (const float*)d_in[7];
    const float* bv = (const float*)d_in[8];
    const float* Wo = (const float*)d_in[9];
    const float* bo = (const float*)d_in[10];
    float* out = (float*)d_out;

    (void)in_sizes; (void)n_in; (void)out_size;

    // 1) QKV projections (Q,K written transposed [B,H,Dh,S]; V normal)
    proj_qkv_kernel<<<dim3(32, 16, 3), 256>>>(q, k, v, Wq, Wk, Wv, bq, bk, bv);
    // 2) flash attention -> g_ctx  (48KB dynamic smem, within default limit)
    flash_kernel<<<dim3(32, 16, 2), 256, 49152>>>();
    // 3) output projection + bias -> d_out
    outproj_kernel<<<dim3(32, 16), 256>>>(Wo, bo, out);
}